// round 6
// baseline (speedup 1.0000x reference)
#include <cuda_runtime.h>

// SingleDisCoLoss: BCE + 0.1 * weighted dcorr^2 over labels==0 subset. N=8192.
// Round 6: 2 launches.
//   K1 prep: wm, bucket member lists (int atomics only), 7 per-block partials.
//   K2 fused: N^2 P_ab pass (all 1024 blocks) + u/v bucket-scan work (first 64
//             blocks) + last-ticket finalize.
//   P_aa,P_bb closed form; u,v exact via monotone 256-bucket prefix sums;
//   S_XY = P_xy + (2W-4nf)/nf^2 * Q_xy + xt*yt*(4nf^2-4W nf+W^2)

#define MAXN 8192
#define NB   256
#define CAP  256
#define TB4  128
#define ROWS 4
#define GY   64
#define GX   (MAXN / (TB4 * ROWS))          // 16
#define NBLK (GX * GY)                      // 1024
#define UVB  64                             // uv blocks (64 x 128 = 8192 elems)
#define K1B  32
#define K1T  256
#define DISCO_LAMBDA 0.1
#define ABSMASK 0x7FFFFFFF7FFFFFFFULL

typedef unsigned long long ull;

// ---- scratch (device globals; zero at load; re-zeroed by finalize path) ----
__device__ float  g_wm[MAXN];
__device__ int    g_cntp[NB], g_cntt[NB];
__device__ float2 g_mp[NB * CAP], g_mt[NB * CAP];   // {value, wm}
__device__ double g_part[7][K1B];   // bce, nf, W, Sp, Sp2, St, St2
__device__ double g_S[5];           // sa, sb, qab, qaa, qbb (atomic)
__device__ double g_Pab;            // atomic
__device__ unsigned g_ticket;

// ---- helpers --------------------------------------------------------------
__device__ __forceinline__ ull pack2(float a, float b) {
    ull r; asm("mov.b64 %0, {%1, %2};" : "=l"(r) : "f"(a), "f"(b)); return r;
}
__device__ __forceinline__ float lo2(ull x) { return __uint_as_float((unsigned)x); }
__device__ __forceinline__ float hi2(ull x) { return __uint_as_float((unsigned)(x >> 32)); }
#define ADD2(out, a, b) asm("add.rn.f32x2 %0, %1, %2;" : "=l"(out) : "l"(a), "l"(b))
#define MUL2(out, a, b) asm("mul.rn.f32x2 %0, %1, %2;" : "=l"(out) : "l"(a), "l"(b))
#define FMA2(acc, a, b) asm("fma.rn.f32x2 %0, %1, %2, %0;" : "+l"(acc) : "l"(a), "l"(b))

__device__ __forceinline__ void warp_red(double& x) {
    #pragma unroll
    for (int o = 16; o > 0; o >>= 1) x += __shfl_down_sync(0xFFFFFFFFu, x, o);
}
__device__ __forceinline__ int buck_p(float p) {
    int b = (int)(p * 256.0f);
    return min(NB - 1, max(0, b));
}
__device__ __forceinline__ int buck_t(float t) {
    int b = (int)((t + 4.5f) * (256.0f / 9.0f));
    return min(NB - 1, max(0, b));
}

// ---------------------------------------------------------------------------
// K1: prep. wm, member lists (int atomics only), 7 per-block partials.
// ---------------------------------------------------------------------------
__global__ void k_prep(const float* __restrict__ p, const int* __restrict__ lab,
                       const float* __restrict__ t, const float* __restrict__ w, int n) {
    int tid = threadIdx.x;
    int idx = blockIdx.x * K1T + tid;

    int   y  = lab[idx];
    float wi = w[idx];
    float wm = (y == 0) ? wi : 0.0f;
    g_wm[idx] = wm;
    float pi = p[idx];
    float ti = t[idx];

    int bp = buck_p(pi);
    int sp_ = atomicAdd(&g_cntp[bp], 1);
    if (sp_ < CAP) g_mp[bp * CAP + sp_] = make_float2(pi, wm);

    int bt = buck_t(ti);
    int st_ = atomicAdd(&g_cntt[bt], 1);
    if (st_ < CAP) g_mt[bt * CAP + st_] = make_float2(ti, wm);

    float logp   = fmaxf(logf(pi),    -100.0f);
    float log1mp = fmaxf(log1pf(-pi), -100.0f);
    float loss   = (y != 0) ? -logp : -log1mp;

    double acc[7];
    acc[0] = (double)(wi * loss);
    acc[1] = (y == 0) ? 1.0 : 0.0;
    acc[2] = (double)wm;
    acc[3] = (double)wm * pi;
    acc[4] = (double)wm * pi * pi;
    acc[5] = (double)wm * ti;
    acc[6] = (double)wm * ti * ti;

    __shared__ double red[7][8];
    int lane = tid & 31, wid = tid >> 5;
    #pragma unroll
    for (int q = 0; q < 7; q++) warp_red(acc[q]);
    if (lane == 0) {
        #pragma unroll
        for (int q = 0; q < 7; q++) red[q][wid] = acc[q];
    }
    __syncthreads();
    if (tid == 0) {
        #pragma unroll
        for (int q = 0; q < 7; q++) {
            double s = 0;
            #pragma unroll
            for (int k = 0; k < K1T / 32; k++) s += red[q][k];
            g_part[q][blockIdx.x] = s;
        }
    }
}

// ---------------------------------------------------------------------------
// K2: N^2 pass (P_ab) all blocks; uv work on first UVB blocks; last-ticket
//     finalize.
// ---------------------------------------------------------------------------
__global__ void k_pab(const float* __restrict__ p, const float* __restrict__ t,
                      float* __restrict__ out, int n) {
    int tid = threadIdx.x;
    int i0  = blockIdx.x * (TB4 * ROWS) + tid * ROWS;
    int j0  = blockIdx.y * TB4;
    int bid = blockIdx.y * GX + blockIdx.x;   // flat block id

    float4 pv = *(const float4*)(p + i0);
    float4 tv = *(const float4*)(t + i0);
    ull pA0 = pack2(pv.x, pv.y), pA1 = pack2(pv.z, pv.w);
    ull tA0 = pack2(tv.x, tv.y), tA1 = pack2(tv.z, tv.w);

    __shared__ ulonglong2 sPT[TB4];  // {-pj dup, -tj dup}
    __shared__ ull        sW[TB4];   // {wm_j dup}
    {
        int j = j0 + tid;
        float pj = p[j], tj = t[j], wj = g_wm[j];
        sPT[tid] = make_ulonglong2(pack2(-pj, -pj), pack2(-tj, -tj));
        sW[tid]  = pack2(wj, wj);
    }
    __syncthreads();

    ull ab0 = 0, ab1 = 0;
    #pragma unroll 8
    for (int k = 0; k < TB4; k++) {
        ulonglong2 pt = sPT[k];
        ull wk = sW[k];
        ull dA, dB, m;
        ADD2(dA, pA0, pt.x);
        ADD2(dB, tA0, pt.y);
        MUL2(m, dA, dB); m &= ABSMASK;   // |dp*dt| == |dp||dt|
        FMA2(ab0, m, wk);
        ADD2(dA, pA1, pt.x);
        ADD2(dB, tA1, pt.y);
        MUL2(m, dA, dB); m &= ABSMASK;
        FMA2(ab1, m, wk);
    }

    double w0 = (double)g_wm[i0 + 0], w1 = (double)g_wm[i0 + 1];
    double w2 = (double)g_wm[i0 + 2], w3 = (double)g_wm[i0 + 3];
    double dAB = w0 * lo2(ab0) + w1 * hi2(ab0) + w2 * lo2(ab1) + w3 * hi2(ab1);

    __shared__ double red4[4];
    int lane = tid & 31, wid = tid >> 5;
    warp_red(dAB);
    if (lane == 0) red4[wid] = dAB;
    __syncthreads();
    if (tid == 0) atomicAdd(&g_Pab, red4[0] + red4[1] + red4[2] + red4[3]);

    // ---- uv phase: first UVB blocks compute exact u,v for 128 elements ----
    if (bid < UVB) {
        __shared__ double sIWp[NB], sIXp[NB], sIWt[NB], sIXt[NB];
        __shared__ double sRWp[NB], sRXp[NB], sRWt[NB], sRXt[NB];

        // bucket sums from member lists (thread handles buckets tid, tid+128)
        #pragma unroll
        for (int rep = 0; rep < 2; rep++) {
            int b = tid + rep * TB4;
            {
                int c = min(g_cntp[b], CAP);
                const float2* m = &g_mp[b * CAP];
                double Wb = 0, Xb = 0;
                #pragma unroll 4
                for (int k = 0; k < c; k++) {
                    float2 e = m[k];
                    Wb += (double)e.y;
                    Xb += (double)e.y * (double)e.x;
                }
                sRWp[b] = Wb; sIWp[b] = Wb;
                sRXp[b] = Xb; sIXp[b] = Xb;
            }
            {
                int c = min(g_cntt[b], CAP);
                const float2* m = &g_mt[b * CAP];
                double Wb = 0, Xb = 0;
                #pragma unroll 4
                for (int k = 0; k < c; k++) {
                    float2 e = m[k];
                    Wb += (double)e.y;
                    Xb += (double)e.y * (double)e.x;
                }
                sRWt[b] = Wb; sIWt[b] = Wb;
                sRXt[b] = Xb; sIXt[b] = Xb;
            }
        }
        __syncthreads();

        // inclusive Hillis-Steele scan over 256 entries, 128 threads (2/thread)
        for (int off = 1; off < NB; off <<= 1) {
            int iA = tid, iB = tid + TB4;
            double a0 = 0, a1 = 0, b0_ = 0, b1_ = 0, c0 = 0, c1 = 0, d0 = 0, d1 = 0;
            if (iA >= off) { a0 = sIWp[iA - off]; b0_ = sIXp[iA - off]; c0 = sIWt[iA - off]; d0 = sIXt[iA - off]; }
            { a1 = sIWp[iB - off]; b1_ = sIXp[iB - off]; c1 = sIWt[iB - off]; d1 = sIXt[iB - off]; }
            __syncthreads();
            if (iA >= off) { sIWp[iA] += a0; sIXp[iA] += b0_; sIWt[iA] += c0; sIXt[iA] += d0; }
            sIWp[iB] += a1; sIXp[iB] += b1_; sIWt[iB] += c1; sIXt[iB] += d1;
            __syncthreads();
        }

        int i = bid * TB4 + tid;
        float pi  = p[i];
        float ti  = t[i];
        float wmi = g_wm[i];

        double Wtp = sIWp[NB - 1], Xtp = sIXp[NB - 1];
        double Wtt = sIWt[NB - 1], Xtt = sIXt[NB - 1];

        double u;
        {
            int b = buck_p(pi);
            double Wlo = sIWp[b] - sRWp[b];
            double Xlo = sIXp[b] - sRXp[b];
            double Whi = Wtp - sIWp[b];
            double Xhi = Xtp - sIXp[b];
            u = (double)pi * (Wlo - Whi) - Xlo + Xhi;
            int c = min(g_cntp[b], CAP);
            const float2* m = &g_mp[b * CAP];
            float s = 0.0f;
            #pragma unroll 4
            for (int k = 0; k < c; k++) {
                float2 e = m[k];
                s = fmaf(e.y, fabsf(pi - e.x), s);
            }
            u += (double)s;
        }
        double v;
        {
            int b = buck_t(ti);
            double Wlo = sIWt[b] - sRWt[b];
            double Xlo = sIXt[b] - sRXt[b];
            double Whi = Wtt - sIWt[b];
            double Xhi = Xtt - sIXt[b];
            v = (double)ti * (Wlo - Whi) - Xlo + Xhi;
            int c = min(g_cntt[b], CAP);
            const float2* m = &g_mt[b * CAP];
            float s = 0.0f;
            #pragma unroll 4
            for (int k = 0; k < c; k++) {
                float2 e = m[k];
                s = fmaf(e.y, fabsf(ti - e.x), s);
            }
            v += (double)s;
        }

        double acc[5];
        acc[0] = (double)wmi * u;
        acc[1] = (double)wmi * v;
        acc[2] = (double)wmi * u * v;
        acc[3] = (double)wmi * u * u;
        acc[4] = (double)wmi * v * v;

        __shared__ double redq[5][4];
        #pragma unroll
        for (int q = 0; q < 5; q++) warp_red(acc[q]);
        if (lane == 0) {
            #pragma unroll
            for (int q = 0; q < 5; q++) redq[q][wid] = acc[q];
        }
        __syncthreads();
        if (tid == 0) {
            #pragma unroll
            for (int q = 0; q < 5; q++)
                atomicAdd(&g_S[q], redq[q][0] + redq[q][1] + redq[q][2] + redq[q][3]);
        }
    }

    // ---- ticket + finalize ----
    __shared__ bool amLast;
    if (tid == 0) {
        __threadfence();
        unsigned vtk = atomicAdd(&g_ticket, 1u);
        amLast = (vtk == (unsigned)(NBLK - 1));
    }
    __syncthreads();
    if (!amLast) return;

    __shared__ double pr[7];
    if (tid < 7) {
        double s = 0;
        #pragma unroll
        for (int k = 0; k < K1B; k++) s += g_part[tid][k];
        pr[tid] = s;
    }
    __syncthreads();
    if (tid == 0) {
        double bce_s = pr[0], nf = pr[1], W = pr[2];
        double Sp = pr[3], Sp2 = pr[4], St = pr[5], St2 = pr[6];

        double Paa = 2.0 * (W * Sp2 - Sp * Sp);
        double Pbb = 2.0 * (W * St2 - St * St);
        double sa = g_S[0], sb = g_S[1], qab = g_S[2], qaa = g_S[3], qbb = g_S[4];

        double inv2 = 1.0 / (nf * nf);
        double at = sa * inv2;
        double bt = sb * inv2;
        double cQ = (2.0 * W - 4.0 * nf) * inv2;
        double cT = 4.0 * nf * nf - 4.0 * W * nf + W * W;

        double SAB = g_Pab + cQ * qab + at * bt * cT;
        double SAA = Paa   + cQ * qaa + at * at * cT;
        double SBB = Pbb   + cQ * qbb + bt * bt * cT;

        double bce   = bce_s / (double)n;
        double dcorr = (SAB * SAB) / (SAA * SBB);
        double ld    = DISCO_LAMBDA * dcorr;
        out[0] = (float)(bce + ld);
        out[1] = (float)bce;
        out[2] = (float)ld;
    }
    // re-zero scratch for next graph replay
    for (int b = tid; b < NB; b += TB4) { g_cntp[b] = 0; g_cntt[b] = 0; }
    if (tid < 5) g_S[tid] = 0.0;
    if (tid == 0) { g_Pab = 0.0; g_ticket = 0u; }
}

// ---------------------------------------------------------------------------
extern "C" void kernel_launch(void* const* d_in, const int* in_sizes, int n_in,
                              void* d_out, int out_size) {
    const float* p   = (const float*)d_in[0];  // inferences
    const int*   lab = (const int*)  d_in[1];  // labels
    const float* t   = (const float*)d_in[2];  // disco_target
    const float* w   = (const float*)d_in[3];  // weights
    float* out = (float*)d_out;
    int n = in_sizes[0];

    k_prep<<<K1B, K1T>>>(p, lab, t, w, n);
    dim3 grid(GX, GY);   // 16 x 64 = 1024 blocks of 128
    k_pab<<<grid, TB4>>>(p, t, out, n);
}